// round 12
// baseline (speedup 1.0000x reference)
#include <cuda_runtime.h>
#include <cuda_fp16.h>
#include <cstdint>
#include <math.h>

#define N_TOT   131072
#define D       512
#define DA      256
#define NH      4
#define NC      53
#define BAG     16
#define NBAGS   8192

#define MT      64          // CTA rows (4 bags)
#define KCH     32          // K chunk (64 bytes fp16) -- double buffered
#define NCHUNK  (D / KCH)   // 16

// ---------------------------------------------------------------------------
// device scratch (allocation is forbidden)
// ---------------------------------------------------------------------------
__device__ float g_WcT[NC * D];
__device__ __align__(256) __half g_W1hH[DA * D];   // W1^T fp16, (n, k) k-contig

// ---------------------------------------------------------------------------
// helpers
// ---------------------------------------------------------------------------
__device__ __forceinline__ uint32_t smem_u32(const void* p) {
    uint32_t a;
    asm("{ .reg .u64 t; cvta.to.shared.u64 t, %1; cvt.u32.u64 %0, t; }" : "=r"(a) : "l"(p));
    return a;
}
__device__ __forceinline__ uint32_t sw128(uint32_t o) { return o ^ ((o >> 3) & 0x70); }
__device__ __forceinline__ uint32_t sw64 (uint32_t o) { return o ^ ((o >> 3) & 0x30); }

#define CP_ASYNC16(dst, src) \
    asm volatile("cp.async.cg.shared.global [%0], [%1], 16;" :: "r"(dst), "l"(src) : "memory")
#define CP_COMMIT() asm volatile("cp.async.commit_group;" ::: "memory")
#define CP_WAIT1()  asm volatile("cp.async.wait_group 1;" ::: "memory")
#define CP_WAIT0()  asm volatile("cp.async.wait_group 0;" ::: "memory")

__device__ __forceinline__ void ldsm_x4(uint32_t& r0, uint32_t& r1, uint32_t& r2,
                                        uint32_t& r3, uint32_t addr) {
    asm volatile("ldmatrix.sync.aligned.m8n8.x4.shared.b16 {%0,%1,%2,%3}, [%4];"
                 : "=r"(r0), "=r"(r1), "=r"(r2), "=r"(r3) : "r"(addr));
}
__device__ __forceinline__ void mma_f16(float* d, const uint32_t* a, const uint32_t* b) {
    asm volatile("mma.sync.aligned.m16n8k16.row.col.f32.f16.f16.f32 "
                 "{%0,%1,%2,%3}, {%4,%5,%6,%7}, {%8,%9}, {%0,%1,%2,%3};"
                 : "+f"(d[0]), "+f"(d[1]), "+f"(d[2]), "+f"(d[3])
                 : "r"(a[0]), "r"(a[1]), "r"(a[2]), "r"(a[3]), "r"(b[0]), "r"(b[1]));
}
__device__ __forceinline__ float ftanh(float v) {
    float e2 = __expf(2.0f * v);
    return 1.0f - __fdividef(2.0f, e2 + 1.0f);
}
__device__ __forceinline__ uint32_t pack_h2(float a, float b) {
    __half2 h = __floats2half2_rn(a, b);
    return *reinterpret_cast<uint32_t*>(&h);
}

// ---------------------------------------------------------------------------
// prep kernel (merged): W1 -> fp16 transpose; Wc -> transpose
// blocks [0,512): W1 (512*256 elems); blocks [512, 512+106): Wc
// ---------------------------------------------------------------------------
__global__ void prep_kernel(const float* __restrict__ W1,
                            const float* __restrict__ Wc) {
    int b = blockIdx.x;
    if (b < 512) {
        int i = b * 256 + threadIdx.x;        // over D*DA, (k, n) in
        int k = i >> 8, n = i & 255;
        g_W1hH[n * D + k] = __float2half_rn(W1[i]);
    } else {
        int i = (b - 512) * 256 + threadIdx.x;
        if (i < D * NC) {
            int d = i / NC, c = i - d * NC;
            g_WcT[c * D + d] = Wc[i];
        }
    }
}

// ---------------------------------------------------------------------------
// fused kernel: fp16 GEMM (64x256x512) + tanh/W2 + bag softmax
//               + bag weighted-sum (from resident fp16 A) + classifier
// smem layout (bytes):
//   0      W2s      4096   (float4[256])
//   4096   sRed4    4096   ([4][64][4] float)
//   8192   sw       256    (w[64])
//   8704   A        65536  (8 sub-tiles, 64 rows x 128B, sw128)
//   74240  B        2 x 16384 (256 n-rows x 64B, sw64)  -- reused as rep[4][512]
// ---------------------------------------------------------------------------
#define SO_W2    0
#define SO_RED   4096
#define SO_SW    8192
#define SOF_A    8704
#define SOF_B    74240
#define BSTG     16384
#define SO_REP   SOF_B
#define SMEM_SZ  (SOF_B + 2 * BSTG)   // 107008

__global__ void __launch_bounds__(256, 2) fused_kernel(
    const float* __restrict__ x,
    const float* __restrict__ W2,
    const float* __restrict__ bc,
    float* __restrict__ out)
{
    extern __shared__ char smem[];
    const uint32_t sb = smem_u32(smem);
    const int tid  = threadIdx.x;
    const int warp = tid >> 5;
    const int lane = tid & 31;
    const int wm = warp & 1;        // 0..1 : 32-row group
    const int wn = warp >> 1;       // 0..3 : 64-col group
    const size_t rowBase = (size_t)blockIdx.x * MT;
    const float* xrow = x + rowBase * D;

    float4* W2s = (float4*)(smem + SO_W2);
    for (int i = tid; i < DA; i += 256) W2s[i] = ((const float4*)W2)[i];

    // ---- prologue: B chunks 0,1 via cp.async (4 x 16B per thread each) ----
#pragma unroll
    for (int i = 0; i < 4; i++) {
        int f = tid + i * 256;            // 1024 x 16B
        int n = f >> 2, k8 = f & 3;       // k8: 8-elem group within 32k
        CP_ASYNC16(sb + SOF_B + sw64((uint32_t)(n * 64 + k8 * 16)),
                   g_W1hH + n * D + k8 * 8);
    }
    CP_COMMIT();
#pragma unroll
    for (int i = 0; i < 4; i++) {
        int f = tid + i * 256;
        int n = f >> 2, k8 = f & 3;
        CP_ASYNC16(sb + SOF_B + BSTG + sw64((uint32_t)(n * 64 + k8 * 16)),
                   g_W1hH + n * D + KCH + k8 * 8);
    }
    CP_COMMIT();

    // ---- full A tile: ldg fp32 -> fp16 -> STS (8 sub-tiles, sw128) ----
#pragma unroll
    for (int i = 0; i < 32; i++) {
        int f  = tid + i * 256;          // float4 idx over 8192
        int r  = f >> 7;
        int k4 = (f & 127) << 2;
        float4 v = *(const float4*)&xrow[(size_t)r * D + k4];
        int chunk = k4 >> 6;
        int inner = (k4 & 63) << 1;
        *(uint2*)(smem + SOF_A + chunk * 8192 + sw128((uint32_t)(r * 128 + inner))) =
            make_uint2(pack_h2(v.x, v.y), pack_h2(v.z, v.w));
    }

    float acc[2][8][4];
#pragma unroll
    for (int mt = 0; mt < 2; mt++)
#pragma unroll
        for (int nt = 0; nt < 8; nt++)
#pragma unroll
            for (int q = 0; q < 4; q++) acc[mt][nt][q] = 0.0f;

    // ---- main loop: 16 chunks of K=32, B double-buffered ----
    for (int c = 0; c < NCHUNK; c++) {
        if (c + 1 < NCHUNK) CP_WAIT1(); else CP_WAIT0();
        __syncthreads();

        const uint32_t stgA = sb + SOF_A + (c >> 1) * 8192;
        const int      abyte = (c & 1) * 64;           // byte-half within 128B A row
        const uint32_t stgB = sb + SOF_B + (c & 1) * BSTG;

#pragma unroll
        for (int ks = 0; ks < 2; ks++) {
            const int kbA = abyte + ks * 32;
            const int kbB = ks * 32;
            uint32_t ah[2][4];
#pragma unroll
            for (int mt = 0; mt < 2; mt++) {
                int row = wm * 32 + mt * 16 + ((lane >> 3) & 1) * 8 + (lane & 7);
                int kh  = (lane >> 4) * 8;
                ldsm_x4(ah[mt][0], ah[mt][1], ah[mt][2], ah[mt][3],
                        stgA + sw128((uint32_t)(row * 128 + kbA + kh * 2)));
            }
            uint32_t bh[8][2];
#pragma unroll
            for (int np = 0; np < 4; np++) {
                int nrow = wn * 64 + np * 16 + (lane >> 4) * 8 + (lane & 7);
                int kh   = ((lane >> 3) & 1) * 8;
                ldsm_x4(bh[2*np][0], bh[2*np][1], bh[2*np+1][0], bh[2*np+1][1],
                        stgB + sw64((uint32_t)(nrow * 64 + kbB + kh * 2)));
            }
#pragma unroll
            for (int mt = 0; mt < 2; mt++)
#pragma unroll
                for (int nt = 0; nt < 8; nt++) mma_f16(acc[mt][nt], ah[mt], bh[nt]);
        }
        __syncthreads();

        if (c + 2 < NCHUNK) {
#pragma unroll
            for (int i = 0; i < 4; i++) {
                int f = tid + i * 256;
                int n = f >> 2, k8 = f & 3;
                CP_ASYNC16(sb + SOF_B + (c & 1) * BSTG +
                               sw64((uint32_t)(n * 64 + k8 * 16)),
                           g_W1hH + n * D + (c + 2) * KCH + k8 * 8);
            }
            CP_COMMIT();
        }
    }

    // ---- epilogue 1: tanh -> x W2 partials -> cross-warp reduce ----
    const int gid = lane >> 2, tig = lane & 3;
    float* sRed4 = (float*)(smem + SO_RED);   // [wn][64][4]

#pragma unroll
    for (int mt = 0; mt < 2; mt++) {
        float p0[4] = {0, 0, 0, 0}, p1[4] = {0, 0, 0, 0};
#pragma unroll
        for (int nt = 0; nt < 8; nt++) {
            int col = wn * 64 + nt * 8 + tig * 2;
            float4 wa = W2s[col], wb = W2s[col + 1];
            float t0 = ftanh(acc[mt][nt][0]);
            float t1 = ftanh(acc[mt][nt][1]);
            float t2 = ftanh(acc[mt][nt][2]);
            float t3 = ftanh(acc[mt][nt][3]);
            p0[0] = fmaf(t0, wa.x, fmaf(t1, wb.x, p0[0]));
            p0[1] = fmaf(t0, wa.y, fmaf(t1, wb.y, p0[1]));
            p0[2] = fmaf(t0, wa.z, fmaf(t1, wb.z, p0[2]));
            p0[3] = fmaf(t0, wa.w, fmaf(t1, wb.w, p0[3]));
            p1[0] = fmaf(t2, wa.x, fmaf(t3, wb.x, p1[0]));
            p1[1] = fmaf(t2, wa.y, fmaf(t3, wb.y, p1[1]));
            p1[2] = fmaf(t2, wa.z, fmaf(t3, wb.z, p1[2]));
            p1[3] = fmaf(t2, wa.w, fmaf(t3, wb.w, p1[3]));
        }
#pragma unroll
        for (int h = 0; h < 4; h++) {
            p0[h] += __shfl_xor_sync(0xffffffffu, p0[h], 1);
            p0[h] += __shfl_xor_sync(0xffffffffu, p0[h], 2);
            p1[h] += __shfl_xor_sync(0xffffffffu, p1[h], 1);
            p1[h] += __shfl_xor_sync(0xffffffffu, p1[h], 2);
        }
        if (tig == 0) {
            int r0 = wm * 32 + mt * 16 + gid;
            int r1 = r0 + 8;
#pragma unroll
            for (int h = 0; h < 4; h++) {
                sRed4[(wn * 64 + r0) * 4 + h] = p0[h];
                sRed4[(wn * 64 + r1) * 4 + h] = p1[h];
            }
        }
    }
    __syncthreads();

    // ---- epilogue 2: per-bag softmax (16-lane groups), head-mean weight ----
    float* sw = (float*)(smem + SO_SW);
    if (tid < MT) {
        float sc[4];
#pragma unroll
        for (int h = 0; h < 4; h++)
            sc[h] = sRed4[(0 * 64 + tid) * 4 + h] + sRed4[(1 * 64 + tid) * 4 + h]
                  + sRed4[(2 * 64 + tid) * 4 + h] + sRed4[(3 * 64 + tid) * 4 + h];
        float wsum = 0.f;
#pragma unroll
        for (int h = 0; h < 4; h++) {
            float mx = sc[h];
#pragma unroll
            for (int o = 1; o < 16; o <<= 1)
                mx = fmaxf(mx, __shfl_xor_sync(0xffffffffu, mx, o));
            float e = __expf(sc[h] - mx);
            float den = e;
#pragma unroll
            for (int o = 1; o < 16; o <<= 1)
                den += __shfl_xor_sync(0xffffffffu, den, o);
            wsum += e / den;
        }
        sw[tid] = 0.25f * wsum;
    }
    __syncthreads();

    // ---- epilogue 3: bag weighted sums from resident fp16 A ----
    {
        const int bag = tid >> 6;
        const int cg  = tid & 63;
        const int chunk = cg >> 3;
        const int innerb = (cg & 7) * 16;
        const uint32_t abase = sb + SOF_A + chunk * 8192;

        float a8[8];
#pragma unroll
        for (int j = 0; j < 8; j++) a8[j] = 0.f;
#pragma unroll
        for (int r = 0; r < BAG; r++) {
            int row = bag * BAG + r;
            float w = sw[row];
            uint4 v;
            asm volatile("ld.shared.v4.u32 {%0,%1,%2,%3}, [%4];"
                         : "=r"(v.x), "=r"(v.y), "=r"(v.z), "=r"(v.w)
                         : "r"(abase + sw128((uint32_t)(row * 128 + innerb))));
            const __half2* h2 = (const __half2*)&v;
#pragma unroll
            for (int q = 0; q < 4; q++) {
                float2 f2 = __half22float2(h2[q]);
                a8[2*q]   = fmaf(w, f2.x, a8[2*q]);
                a8[2*q+1] = fmaf(w, f2.y, a8[2*q+1]);
            }
        }
        __syncthreads();   // done reading A/B; rep aliases B
        float* rep = (float*)(smem + SO_REP);
        int base = bag * D + cg * 8;
#pragma unroll
        for (int j = 0; j < 8; j++) rep[base + j] = a8[j];
    }
    __syncthreads();

    // ---- epilogue 4: classifier  logits = rep @ WcT + bc ----
    {
        const float4* rep4 = (const float4*)(smem + SO_REP);
        for (int p = warp; p < 4 * NC; p += 8) {
            const int bag = p / NC;
            const int c   = p - bag * NC;
            const float4* wc = (const float4*)&g_WcT[c * D];
            const float4* rp = &rep4[bag * 128];
            float s = 0.0f;
#pragma unroll
            for (int q = 0; q < 4; q++) {
                int i = lane + q * 32;
                float4 rv = rp[i];
                float4 wv = wc[i];
                s = fmaf(rv.x, wv.x, s);
                s = fmaf(rv.y, wv.y, s);
                s = fmaf(rv.z, wv.z, s);
                s = fmaf(rv.w, wv.w, s);
            }
            s += __shfl_xor_sync(0xffffffffu, s, 16);
            s += __shfl_xor_sync(0xffffffffu, s, 8);
            s += __shfl_xor_sync(0xffffffffu, s, 4);
            s += __shfl_xor_sync(0xffffffffu, s, 2);
            s += __shfl_xor_sync(0xffffffffu, s, 1);
            if (lane == 0)
                out[((size_t)blockIdx.x * 4 + bag) * NC + c] = s + bc[c];
        }
    }
}

// ---------------------------------------------------------------------------
extern "C" void kernel_launch(void* const* d_in, const int* in_sizes, int n_in,
                              void* d_out, int out_size)
{
    const float* x  = (const float*)d_in[0];
    const float* W1 = (const float*)d_in[1];
    const float* W2 = (const float*)d_in[2];
    const float* Wc = (const float*)d_in[3];
    const float* bc = (const float*)d_in[4];
    float* out = (float*)d_out;

    cudaFuncSetAttribute(fused_kernel,
                         cudaFuncAttributeMaxDynamicSharedMemorySize, SMEM_SZ);

    prep_kernel<<<512 + (D * NC + 255) / 256, 256>>>(W1, Wc);
    fused_kernel<<<N_TOT / MT, 256, SMEM_SZ>>>(x, W2, bc, out);
}

// round 13
// speedup vs baseline: 1.2449x; 1.2449x over previous
#include <cuda_runtime.h>
#include <cuda_fp16.h>
#include <cstdint>
#include <math.h>

#define N_TOT   131072
#define D       512
#define DA      256
#define NH      4
#define NC      53
#define BAG     16
#define NBAGS   8192

#define MT      64          // CTA rows (4 bags)
#define KCH     32          // K chunk (64 bytes fp16) -- double buffered
#define NCHUNK  (D / KCH)   // 16

// ---------------------------------------------------------------------------
// device scratch (allocation is forbidden)
// ---------------------------------------------------------------------------
__device__ float g_WcT[NC * D];
__device__ float g_rep[NBAGS * D];                 // bag representations
__device__ __align__(256) __half g_W1hH[DA * D];   // W1^T fp16, (n, k) k-contig

// ---------------------------------------------------------------------------
// helpers
// ---------------------------------------------------------------------------
__device__ __forceinline__ uint32_t smem_u32(const void* p) {
    uint32_t a;
    asm("{ .reg .u64 t; cvta.to.shared.u64 t, %1; cvt.u32.u64 %0, t; }" : "=r"(a) : "l"(p));
    return a;
}
__device__ __forceinline__ uint32_t sw128(uint32_t o) { return o ^ ((o >> 3) & 0x70); }
__device__ __forceinline__ uint32_t sw64 (uint32_t o) { return o ^ ((o >> 3) & 0x30); }

#define CP_ASYNC16(dst, src) \
    asm volatile("cp.async.cg.shared.global [%0], [%1], 16;" :: "r"(dst), "l"(src) : "memory")
#define CP_COMMIT() asm volatile("cp.async.commit_group;" ::: "memory")
#define CP_WAIT1()  asm volatile("cp.async.wait_group 1;" ::: "memory")
#define CP_WAIT0()  asm volatile("cp.async.wait_group 0;" ::: "memory")

__device__ __forceinline__ void ldsm_x4(uint32_t& r0, uint32_t& r1, uint32_t& r2,
                                        uint32_t& r3, uint32_t addr) {
    asm volatile("ldmatrix.sync.aligned.m8n8.x4.shared.b16 {%0,%1,%2,%3}, [%4];"
                 : "=r"(r0), "=r"(r1), "=r"(r2), "=r"(r3) : "r"(addr));
}
__device__ __forceinline__ void mma_f16(float* d, const uint32_t* a, const uint32_t* b) {
    asm volatile("mma.sync.aligned.m16n8k16.row.col.f32.f16.f16.f32 "
                 "{%0,%1,%2,%3}, {%4,%5,%6,%7}, {%8,%9}, {%0,%1,%2,%3};"
                 : "+f"(d[0]), "+f"(d[1]), "+f"(d[2]), "+f"(d[3])
                 : "r"(a[0]), "r"(a[1]), "r"(a[2]), "r"(a[3]), "r"(b[0]), "r"(b[1]));
}
__device__ __forceinline__ float ftanh(float v) {
    float e2 = __expf(2.0f * v);
    return 1.0f - __fdividef(2.0f, e2 + 1.0f);
}
__device__ __forceinline__ uint32_t pack_h2(float a, float b) {
    __half2 h = __floats2half2_rn(a, b);
    return *reinterpret_cast<uint32_t*>(&h);
}

// ---------------------------------------------------------------------------
// prep kernel (merged): W1 -> fp16 transpose; Wc -> transpose
// ---------------------------------------------------------------------------
__global__ void prep_kernel(const float* __restrict__ W1,
                            const float* __restrict__ Wc) {
    int b = blockIdx.x;
    if (b < 512) {
        int i = b * 256 + threadIdx.x;
        int k = i >> 8, n = i & 255;
        g_W1hH[n * D + k] = __float2half_rn(W1[i]);
    } else {
        int i = (b - 512) * 256 + threadIdx.x;
        if (i < D * NC) {
            int d = i / NC, c = i - d * NC;
            g_WcT[c * D + d] = Wc[i];
        }
    }
}

// ---------------------------------------------------------------------------
// fused kernel: fp16 GEMM (64x256x512) + tanh/W2 + bag softmax
//               + bag weighted-sum (resident fp16 A) -> g_rep
// smem: 0 W2s 4K | 4096 sRed4 4K | 8192 sw 256 | 8704 A 64K | 74240 B 2x16K
// ---------------------------------------------------------------------------
#define SO_W2    0
#define SO_RED   4096
#define SO_SW    8192
#define SOF_A    8704
#define SOF_B    74240
#define BSTG     16384
#define SMEM_SZ  (SOF_B + 2 * BSTG)   // 107008

__global__ void __launch_bounds__(256, 2) fused_kernel(
    const float* __restrict__ x,
    const float* __restrict__ W2)
{
    extern __shared__ char smem[];
    const uint32_t sb = smem_u32(smem);
    const int tid  = threadIdx.x;
    const int warp = tid >> 5;
    const int lane = tid & 31;
    const int wm = warp & 1;        // 0..1 : 32-row group
    const int wn = warp >> 1;       // 0..3 : 64-col group
    const size_t rowBase = (size_t)blockIdx.x * MT;
    const float* xrow = x + rowBase * D;

    float4* W2s = (float4*)(smem + SO_W2);
    for (int i = tid; i < DA; i += 256) W2s[i] = ((const float4*)W2)[i];

    // ---- prologue: B chunks 0,1 via cp.async ----
#pragma unroll
    for (int i = 0; i < 4; i++) {
        int f = tid + i * 256;
        int n = f >> 2, k8 = f & 3;
        CP_ASYNC16(sb + SOF_B + sw64((uint32_t)(n * 64 + k8 * 16)),
                   g_W1hH + n * D + k8 * 8);
    }
    CP_COMMIT();
#pragma unroll
    for (int i = 0; i < 4; i++) {
        int f = tid + i * 256;
        int n = f >> 2, k8 = f & 3;
        CP_ASYNC16(sb + SOF_B + BSTG + sw64((uint32_t)(n * 64 + k8 * 16)),
                   g_W1hH + n * D + KCH + k8 * 8);
    }
    CP_COMMIT();

    // ---- full A tile: ldg fp32 -> fp16 -> STS (8 sub-tiles, sw128) ----
#pragma unroll
    for (int i = 0; i < 32; i++) {
        int f  = tid + i * 256;
        int r  = f >> 7;
        int k4 = (f & 127) << 2;
        float4 v = *(const float4*)&xrow[(size_t)r * D + k4];
        int chunk = k4 >> 6;
        int inner = (k4 & 63) << 1;
        *(uint2*)(smem + SOF_A + chunk * 8192 + sw128((uint32_t)(r * 128 + inner))) =
            make_uint2(pack_h2(v.x, v.y), pack_h2(v.z, v.w));
    }

    float acc[2][8][4];
#pragma unroll
    for (int mt = 0; mt < 2; mt++)
#pragma unroll
        for (int nt = 0; nt < 8; nt++)
#pragma unroll
            for (int q = 0; q < 4; q++) acc[mt][nt][q] = 0.0f;

    // ---- precomputed swizzled LDSM base offsets (per-thread constants) ----
    // A: sw128(row*128 + kh*2); later addr = stgA + (preA ^ kb), kb in {0,32,64,96}
    uint32_t preA[2];
#pragma unroll
    for (int mt = 0; mt < 2; mt++) {
        int row = wm * 32 + mt * 16 + ((lane >> 3) & 1) * 8 + (lane & 7);
        int kh  = (lane >> 4) * 8;
        preA[mt] = sw128((uint32_t)(row * 128 + kh * 2));
    }
    // B: sw64(nrow*64 + kh*2); addr = stgB + (preB ^ kb), kb in {0,32}
    uint32_t preB[4];
#pragma unroll
    for (int np = 0; np < 4; np++) {
        int nrow = wn * 64 + np * 16 + (lane >> 4) * 8 + (lane & 7);
        int kh   = ((lane >> 3) & 1) * 8;
        preB[np] = sw64((uint32_t)(nrow * 64 + kh * 2));
    }

    // ---- main loop: 16 chunks of K=32, B double-buffered ----
    for (int c = 0; c < NCHUNK; c++) {
        if (c + 1 < NCHUNK) CP_WAIT1(); else CP_WAIT0();
        __syncthreads();

        const uint32_t stgA = sb + SOF_A + (c >> 1) * 8192;
        const uint32_t abyte = (uint32_t)((c & 1) * 64);
        const uint32_t stgB = sb + SOF_B + (c & 1) * BSTG;

#pragma unroll
        for (int ks = 0; ks < 2; ks++) {
            const uint32_t kbA = abyte + ks * 32;
            const uint32_t kbB = (uint32_t)(ks * 32);
            uint32_t ah[2][4];
#pragma unroll
            for (int mt = 0; mt < 2; mt++)
                ldsm_x4(ah[mt][0], ah[mt][1], ah[mt][2], ah[mt][3],
                        stgA + (preA[mt] ^ kbA));
            uint32_t bh[8][2];
#pragma unroll
            for (int np = 0; np < 4; np++)
                ldsm_x4(bh[2*np][0], bh[2*np][1], bh[2*np+1][0], bh[2*np+1][1],
                        stgB + (preB[np] ^ kbB));
#pragma unroll
            for (int mt = 0; mt < 2; mt++)
#pragma unroll
                for (int nt = 0; nt < 8; nt++) mma_f16(acc[mt][nt], ah[mt], bh[nt]);
        }
        __syncthreads();

        if (c + 2 < NCHUNK) {
#pragma unroll
            for (int i = 0; i < 4; i++) {
                int f = tid + i * 256;
                int n = f >> 2, k8 = f & 3;
                CP_ASYNC16(sb + SOF_B + (c & 1) * BSTG +
                               sw64((uint32_t)(n * 64 + k8 * 16)),
                           g_W1hH + n * D + (c + 2) * KCH + k8 * 8);
            }
            CP_COMMIT();
        }
    }

    // ---- epilogue 1: tanh -> x W2 partials -> cross-warp reduce ----
    const int gid = lane >> 2, tig = lane & 3;
    float* sRed4 = (float*)(smem + SO_RED);   // [wn][64][4]

#pragma unroll
    for (int mt = 0; mt < 2; mt++) {
        float p0[4] = {0, 0, 0, 0}, p1[4] = {0, 0, 0, 0};
#pragma unroll
        for (int nt = 0; nt < 8; nt++) {
            int col = wn * 64 + nt * 8 + tig * 2;
            float4 wa = W2s[col], wb = W2s[col + 1];
            float t0 = ftanh(acc[mt][nt][0]);
            float t1 = ftanh(acc[mt][nt][1]);
            float t2 = ftanh(acc[mt][nt][2]);
            float t3 = ftanh(acc[mt][nt][3]);
            p0[0] = fmaf(t0, wa.x, fmaf(t1, wb.x, p0[0]));
            p0[1] = fmaf(t0, wa.y, fmaf(t1, wb.y, p0[1]));
            p0[2] = fmaf(t0, wa.z, fmaf(t1, wb.z, p0[2]));
            p0[3] = fmaf(t0, wa.w, fmaf(t1, wb.w, p0[3]));
            p1[0] = fmaf(t2, wa.x, fmaf(t3, wb.x, p1[0]));
            p1[1] = fmaf(t2, wa.y, fmaf(t3, wb.y, p1[1]));
            p1[2] = fmaf(t2, wa.z, fmaf(t3, wb.z, p1[2]));
            p1[3] = fmaf(t2, wa.w, fmaf(t3, wb.w, p1[3]));
        }
#pragma unroll
        for (int h = 0; h < 4; h++) {
            p0[h] += __shfl_xor_sync(0xffffffffu, p0[h], 1);
            p0[h] += __shfl_xor_sync(0xffffffffu, p0[h], 2);
            p1[h] += __shfl_xor_sync(0xffffffffu, p1[h], 1);
            p1[h] += __shfl_xor_sync(0xffffffffu, p1[h], 2);
        }
        if (tig == 0) {
            int r0 = wm * 32 + mt * 16 + gid;
            int r1 = r0 + 8;
#pragma unroll
            for (int h = 0; h < 4; h++) {
                sRed4[(wn * 64 + r0) * 4 + h] = p0[h];
                sRed4[(wn * 64 + r1) * 4 + h] = p1[h];
            }
        }
    }
    __syncthreads();

    // ---- epilogue 2: per-bag softmax (16-lane groups), head-mean weight ----
    float* sw = (float*)(smem + SO_SW);
    if (tid < MT) {
        float sc[4];
#pragma unroll
        for (int h = 0; h < 4; h++)
            sc[h] = sRed4[(0 * 64 + tid) * 4 + h] + sRed4[(1 * 64 + tid) * 4 + h]
                  + sRed4[(2 * 64 + tid) * 4 + h] + sRed4[(3 * 64 + tid) * 4 + h];
        float wsum = 0.f;
#pragma unroll
        for (int h = 0; h < 4; h++) {
            float mx = sc[h];
#pragma unroll
            for (int o = 1; o < 16; o <<= 1)
                mx = fmaxf(mx, __shfl_xor_sync(0xffffffffu, mx, o));
            float e = __expf(sc[h] - mx);
            float den = e;
#pragma unroll
            for (int o = 1; o < 16; o <<= 1)
                den += __shfl_xor_sync(0xffffffffu, den, o);
            wsum += e / den;
        }
        sw[tid] = 0.25f * wsum;
    }
    __syncthreads();

    // ---- epilogue 3: bag weighted sums from resident fp16 A -> g_rep ----
    {
        const int bag = tid >> 6;
        const int cg  = tid & 63;
        const int chunk = cg >> 3;
        const int innerb = (cg & 7) * 16;
        const uint32_t abase = sb + SOF_A + chunk * 8192;

        float a8[8];
#pragma unroll
        for (int j = 0; j < 8; j++) a8[j] = 0.f;
#pragma unroll
        for (int r = 0; r < BAG; r++) {
            int row = bag * BAG + r;
            float w = sw[row];
            uint4 v;
            asm volatile("ld.shared.v4.u32 {%0,%1,%2,%3}, [%4];"
                         : "=r"(v.x), "=r"(v.y), "=r"(v.z), "=r"(v.w)
                         : "r"(abase + sw128((uint32_t)(row * 128 + innerb))));
            const __half2* h2 = (const __half2*)&v;
#pragma unroll
            for (int q = 0; q < 4; q++) {
                float2 f2 = __half22float2(h2[q]);
                a8[2*q]   = fmaf(w, f2.x, a8[2*q]);
                a8[2*q+1] = fmaf(w, f2.y, a8[2*q+1]);
            }
        }
        float* dst = g_rep + ((size_t)blockIdx.x * 4 + bag) * D + cg * 8;
        *(float4*)(dst)     = make_float4(a8[0], a8[1], a8[2], a8[3]);
        *(float4*)(dst + 4) = make_float4(a8[4], a8[5], a8[6], a8[7]);
    }
}

// ---------------------------------------------------------------------------
// classifier kernel: out[b, c] = g_rep[b] . g_WcT[c] + bc[c]
// block = 16 bags (32 KB rep in smem); Wc rows held in registers per warp
// ---------------------------------------------------------------------------
#define CLS_BAGS 16
__global__ __launch_bounds__(256) void cls_kernel(
    const float* __restrict__ bc,
    float* __restrict__ out)
{
    __shared__ float rep_s[CLS_BAGS * D];   // 32 KB
    const int tid = threadIdx.x;
    const size_t bagBase = (size_t)blockIdx.x * CLS_BAGS;

    const float4* gr = (const float4*)(g_rep + bagBase * D);
    float4* rs = (float4*)rep_s;
#pragma unroll
    for (int i = 0; i < 8; i++) rs[tid + i * 256] = gr[tid + i * 256];
    __syncthreads();

    const int warp = tid >> 5, lane = tid & 31;
    for (int c = warp; c < NC; c += 8) {
        const float4* wc = (const float4*)&g_WcT[c * D];
        float4 w0 = wc[lane], w1 = wc[lane + 32], w2 = wc[lane + 64], w3 = wc[lane + 96];
        float bcv = bc[c];
#pragma unroll 4
        for (int b = 0; b < CLS_BAGS; b++) {
            const float4* rp = (const float4*)&rep_s[b * D];
            float4 r0 = rp[lane], r1 = rp[lane + 32], r2 = rp[lane + 64], r3 = rp[lane + 96];
            float s = 0.f;
            s = fmaf(r0.x, w0.x, s); s = fmaf(r0.y, w0.y, s);
            s = fmaf(r0.z, w0.z, s); s = fmaf(r0.w, w0.w, s);
            s = fmaf(r1.x, w1.x, s); s = fmaf(r1.y, w1.y, s);
            s = fmaf(r1.z, w1.z, s); s = fmaf(r1.w, w1.w, s);
            s = fmaf(r2.x, w2.x, s); s = fmaf(r2.y, w2.y, s);
            s = fmaf(r2.z, w2.z, s); s = fmaf(r2.w, w2.w, s);
            s = fmaf(r3.x, w3.x, s); s = fmaf(r3.y, w3.y, s);
            s = fmaf(r3.z, w3.z, s); s = fmaf(r3.w, w3.w, s);
            s += __shfl_xor_sync(0xffffffffu, s, 16);
            s += __shfl_xor_sync(0xffffffffu, s, 8);
            s += __shfl_xor_sync(0xffffffffu, s, 4);
            s += __shfl_xor_sync(0xffffffffu, s, 2);
            s += __shfl_xor_sync(0xffffffffu, s, 1);
            if (lane == 0) out[(bagBase + b) * NC + c] = s + bcv;
        }
    }
}

// ---------------------------------------------------------------------------
extern "C" void kernel_launch(void* const* d_in, const int* in_sizes, int n_in,
                              void* d_out, int out_size)
{
    const float* x  = (const float*)d_in[0];
    const float* W1 = (const float*)d_in[1];
    const float* W2 = (const float*)d_in[2];
    const float* Wc = (const float*)d_in[3];
    const float* bc = (const float*)d_in[4];
    float* out = (float*)d_out;

    cudaFuncSetAttribute(fused_kernel,
                         cudaFuncAttributeMaxDynamicSharedMemorySize, SMEM_SZ);

    prep_kernel<<<512 + (D * NC + 255) / 256, 256>>>(W1, Wc);
    fused_kernel<<<N_TOT / MT, 256, SMEM_SZ>>>(x, W2);
    cls_kernel<<<NBAGS / CLS_BAGS, 256>>>(bc, out);
}

// round 14
// speedup vs baseline: 1.3354x; 1.0727x over previous
#include <cuda_runtime.h>
#include <cuda_fp16.h>
#include <cstdint>
#include <math.h>

#define N_TOT   131072
#define D       512
#define DA      256
#define NH      4
#define NC      53
#define BAG     16
#define NBAGS   8192

#define MT      64          // CTA rows (4 bags)
#define KCH     32          // K chunk (64 bytes fp16) -- double buffered
#define NCHUNK  (D / KCH)   // 16

// ---------------------------------------------------------------------------
// device scratch (allocation is forbidden)
// ---------------------------------------------------------------------------
__device__ float g_WcT[NC * D];
__device__ float g_rep[NBAGS * D];                 // bag representations
__device__ __align__(256) __half g_W1hH[DA * D];   // W1^T fp16, (n, k) k-contig

// ---------------------------------------------------------------------------
// helpers
// ---------------------------------------------------------------------------
__device__ __forceinline__ uint32_t smem_u32(const void* p) {
    uint32_t a;
    asm("{ .reg .u64 t; cvta.to.shared.u64 t, %1; cvt.u32.u64 %0, t; }" : "=r"(a) : "l"(p));
    return a;
}
__device__ __forceinline__ uint32_t sw128(uint32_t o) { return o ^ ((o >> 3) & 0x70); }
__device__ __forceinline__ uint32_t sw64 (uint32_t o) { return o ^ ((o >> 3) & 0x30); }

#define CP_ASYNC16(dst, src) \
    asm volatile("cp.async.cg.shared.global [%0], [%1], 16;" :: "r"(dst), "l"(src) : "memory")
#define CP_COMMIT() asm volatile("cp.async.commit_group;" ::: "memory")
#define CP_WAIT0()  asm volatile("cp.async.wait_group 0;" ::: "memory")

__device__ __forceinline__ void ldsm_x4(uint32_t& r0, uint32_t& r1, uint32_t& r2,
                                        uint32_t& r3, uint32_t addr) {
    asm volatile("ldmatrix.sync.aligned.m8n8.x4.shared.b16 {%0,%1,%2,%3}, [%4];"
                 : "=r"(r0), "=r"(r1), "=r"(r2), "=r"(r3) : "r"(addr));
}
__device__ __forceinline__ void mma_f16(float* d, const uint32_t* a, const uint32_t* b) {
    asm volatile("mma.sync.aligned.m16n8k16.row.col.f32.f16.f16.f32 "
                 "{%0,%1,%2,%3}, {%4,%5,%6,%7}, {%8,%9}, {%0,%1,%2,%3};"
                 : "+f"(d[0]), "+f"(d[1]), "+f"(d[2]), "+f"(d[3])
                 : "r"(a[0]), "r"(a[1]), "r"(a[2]), "r"(a[3]), "r"(b[0]), "r"(b[1]));
}
__device__ __forceinline__ float ftanh(float v) {
    float t;
    asm("tanh.approx.f32 %0, %1;" : "=f"(t) : "f"(v));
    return t;
}
__device__ __forceinline__ uint32_t pack_h2(float a, float b) {
    __half2 h = __floats2half2_rn(a, b);
    return *reinterpret_cast<uint32_t*>(&h);
}

// ---------------------------------------------------------------------------
// prep kernel (merged): W1 -> fp16 transpose; Wc -> transpose
// ---------------------------------------------------------------------------
__global__ void prep_kernel(const float* __restrict__ W1,
                            const float* __restrict__ Wc) {
    int b = blockIdx.x;
    if (b < 512) {
        int i = b * 256 + threadIdx.x;
        int k = i >> 8, n = i & 255;
        g_W1hH[n * D + k] = __float2half_rn(W1[i]);
    } else {
        int i = (b - 512) * 256 + threadIdx.x;
        if (i < D * NC) {
            int d = i / NC, c = i - d * NC;
            g_WcT[c * D + d] = Wc[i];
        }
    }
}

// ---------------------------------------------------------------------------
// fused kernel: fp16 GEMM (64x256x512) + tanh/W2 + bag softmax
//               + bag weighted-sum (resident fp16 A) -> g_rep
// smem: 0 W2s 4K | 4096 sRed4 4K | 8192 sw 256 | 8704 A 64K | 74240 B 2x16K
// ---------------------------------------------------------------------------
#define SO_W2    0
#define SO_RED   4096
#define SO_SW    8192
#define SOF_A    8704
#define SOF_B    74240
#define BSTG     16384
#define SMEM_SZ  (SOF_B + 2 * BSTG)   // 107008

__global__ void __launch_bounds__(256, 2) fused_kernel(
    const float* __restrict__ x,
    const float* __restrict__ W2)
{
    extern __shared__ char smem[];
    const uint32_t sb = smem_u32(smem);
    const int tid  = threadIdx.x;
    const int warp = tid >> 5;
    const int lane = tid & 31;
    const int wm = warp & 1;        // 0..1 : 32-row group
    const int wn = warp >> 1;       // 0..3 : 64-col group
    const size_t rowBase = (size_t)blockIdx.x * MT;
    const float* xrow = x + rowBase * D;

    float4* W2s = (float4*)(smem + SO_W2);
    for (int i = tid; i < DA; i += 256) W2s[i] = ((const float4*)W2)[i];

    // ---- prologue: B chunk 0 via cp.async (prefetch distance 1) ----
#pragma unroll
    for (int i = 0; i < 4; i++) {
        int f = tid + i * 256;
        int n = f >> 2, k8 = f & 3;
        CP_ASYNC16(sb + SOF_B + sw64((uint32_t)(n * 64 + k8 * 16)),
                   g_W1hH + n * D + k8 * 8);
    }
    CP_COMMIT();

    // ---- full A tile: ldg fp32 -> fp16 -> STS (8 sub-tiles, sw128) ----
#pragma unroll
    for (int i = 0; i < 32; i++) {
        int f  = tid + i * 256;
        int r  = f >> 7;
        int k4 = (f & 127) << 2;
        float4 v = *(const float4*)&xrow[(size_t)r * D + k4];
        int chunk = k4 >> 6;
        int inner = (k4 & 63) << 1;
        *(uint2*)(smem + SOF_A + chunk * 8192 + sw128((uint32_t)(r * 128 + inner))) =
            make_uint2(pack_h2(v.x, v.y), pack_h2(v.z, v.w));
    }

    float acc[2][8][4];
#pragma unroll
    for (int mt = 0; mt < 2; mt++)
#pragma unroll
        for (int nt = 0; nt < 8; nt++)
#pragma unroll
            for (int q = 0; q < 4; q++) acc[mt][nt][q] = 0.0f;

    // ---- precomputed swizzled LDSM base offsets ----
    uint32_t preA[2];
#pragma unroll
    for (int mt = 0; mt < 2; mt++) {
        int row = wm * 32 + mt * 16 + ((lane >> 3) & 1) * 8 + (lane & 7);
        int kh  = (lane >> 4) * 8;
        preA[mt] = sw128((uint32_t)(row * 128 + kh * 2));
    }
    uint32_t preB[4];
#pragma unroll
    for (int np = 0; np < 4; np++) {
        int nrow = wn * 64 + np * 16 + (lane >> 4) * 8 + (lane & 7);
        int kh   = ((lane >> 3) & 1) * 8;
        preB[np] = sw64((uint32_t)(nrow * 64 + kh * 2));
    }

    // ---- main loop: 16 chunks, ONE barrier per chunk (distance-1 pipe) ----
    for (int c = 0; c < NCHUNK; c++) {
        CP_WAIT0();
        __syncthreads();
        // prefetch next chunk into the opposite stage (safe: all warps have
        // passed this barrier, so nobody still reads stage (c+1)&1 from c-1)
        if (c + 1 < NCHUNK) {
#pragma unroll
            for (int i = 0; i < 4; i++) {
                int f = tid + i * 256;
                int n = f >> 2, k8 = f & 3;
                CP_ASYNC16(sb + SOF_B + ((c + 1) & 1) * BSTG +
                               sw64((uint32_t)(n * 64 + k8 * 16)),
                           g_W1hH + n * D + (c + 1) * KCH + k8 * 8);
            }
            CP_COMMIT();
        }

        const uint32_t stgA = sb + SOF_A + (c >> 1) * 8192;
        const uint32_t abyte = (uint32_t)((c & 1) * 64);
        const uint32_t stgB = sb + SOF_B + (c & 1) * BSTG;

        // batch all A fragments for this chunk (overlap LDSM latency)
        uint32_t ah[2][2][4];
#pragma unroll
        for (int ks = 0; ks < 2; ks++)
#pragma unroll
            for (int mt = 0; mt < 2; mt++)
                ldsm_x4(ah[ks][mt][0], ah[ks][mt][1], ah[ks][mt][2], ah[ks][mt][3],
                        stgA + (preA[mt] ^ (abyte + (uint32_t)(ks * 32))));

#pragma unroll
        for (int ks = 0; ks < 2; ks++) {
            const uint32_t kbB = (uint32_t)(ks * 32);
            uint32_t bh[8][2];
#pragma unroll
            for (int np = 0; np < 4; np++)
                ldsm_x4(bh[2*np][0], bh[2*np][1], bh[2*np+1][0], bh[2*np+1][1],
                        stgB + (preB[np] ^ kbB));
#pragma unroll
            for (int mt = 0; mt < 2; mt++)
#pragma unroll
                for (int nt = 0; nt < 8; nt++)
                    mma_f16(acc[mt][nt], ah[ks][mt], bh[nt]);
        }
    }

    // ---- epilogue 1: tanh -> x W2 partials -> cross-warp reduce ----
    const int gid = lane >> 2, tig = lane & 3;
    float* sRed4 = (float*)(smem + SO_RED);   // [wn][64][4]

#pragma unroll
    for (int mt = 0; mt < 2; mt++) {
        float p0[4] = {0, 0, 0, 0}, p1[4] = {0, 0, 0, 0};
#pragma unroll
        for (int nt = 0; nt < 8; nt++) {
            int col = wn * 64 + nt * 8 + tig * 2;
            float4 wa = W2s[col], wb = W2s[col + 1];
            float t0 = ftanh(acc[mt][nt][0]);
            float t1 = ftanh(acc[mt][nt][1]);
            float t2 = ftanh(acc[mt][nt][2]);
            float t3 = ftanh(acc[mt][nt][3]);
            p0[0] = fmaf(t0, wa.x, fmaf(t1, wb.x, p0[0]));
            p0[1] = fmaf(t0, wa.y, fmaf(t1, wb.y, p0[1]));
            p0[2] = fmaf(t0, wa.z, fmaf(t1, wb.z, p0[2]));
            p0[3] = fmaf(t0, wa.w, fmaf(t1, wb.w, p0[3]));
            p1[0] = fmaf(t2, wa.x, fmaf(t3, wb.x, p1[0]));
            p1[1] = fmaf(t2, wa.y, fmaf(t3, wb.y, p1[1]));
            p1[2] = fmaf(t2, wa.z, fmaf(t3, wb.z, p1[2]));
            p1[3] = fmaf(t2, wa.w, fmaf(t3, wb.w, p1[3]));
        }
#pragma unroll
        for (int h = 0; h < 4; h++) {
            p0[h] += __shfl_xor_sync(0xffffffffu, p0[h], 1);
            p0[h] += __shfl_xor_sync(0xffffffffu, p0[h], 2);
            p1[h] += __shfl_xor_sync(0xffffffffu, p1[h], 1);
            p1[h] += __shfl_xor_sync(0xffffffffu, p1[h], 2);
        }
        if (tig == 0) {
            int r0 = wm * 32 + mt * 16 + gid;
            int r1 = r0 + 8;
#pragma unroll
            for (int h = 0; h < 4; h++) {
                sRed4[(wn * 64 + r0) * 4 + h] = p0[h];
                sRed4[(wn * 64 + r1) * 4 + h] = p1[h];
            }
        }
    }
    __syncthreads();

    // ---- epilogue 2: per-bag softmax (16-lane groups), head-mean weight ----
    float* sw = (float*)(smem + SO_SW);
    if (tid < MT) {
        float sc[4];
#pragma unroll
        for (int h = 0; h < 4; h++)
            sc[h] = sRed4[(0 * 64 + tid) * 4 + h] + sRed4[(1 * 64 + tid) * 4 + h]
                  + sRed4[(2 * 64 + tid) * 4 + h] + sRed4[(3 * 64 + tid) * 4 + h];
        float wsum = 0.f;
#pragma unroll
        for (int h = 0; h < 4; h++) {
            float mx = sc[h];
#pragma unroll
            for (int o = 1; o < 16; o <<= 1)
                mx = fmaxf(mx, __shfl_xor_sync(0xffffffffu, mx, o));
            float e = __expf(sc[h] - mx);
            float den = e;
#pragma unroll
            for (int o = 1; o < 16; o <<= 1)
                den += __shfl_xor_sync(0xffffffffu, den, o);
            wsum += e / den;
        }
        sw[tid] = 0.25f * wsum;
    }
    __syncthreads();

    // ---- epilogue 3: bag weighted sums from resident fp16 A -> g_rep ----
    {
        const int bag = tid >> 6;
        const int cg  = tid & 63;
        const int chunk = cg >> 3;
        const int innerb = (cg & 7) * 16;
        const uint32_t abase = sb + SOF_A + chunk * 8192;

        float a8[8];
#pragma unroll
        for (int j = 0; j < 8; j++) a8[j] = 0.f;
#pragma unroll
        for (int r = 0; r < BAG; r++) {
            int row = bag * BAG + r;
            float w = sw[row];
            uint4 v;
            asm volatile("ld.shared.v4.u32 {%0,%1,%2,%3}, [%4];"
                         : "=r"(v.x), "=r"(v.y), "=r"(v.z), "=r"(v.w)
                         : "r"(abase + sw128((uint32_t)(row * 128 + innerb))));
            const __half2* h2 = (const __half2*)&v;
#pragma unroll
            for (int q = 0; q < 4; q++) {
                float2 f2 = __half22float2(h2[q]);
                a8[2*q]   = fmaf(w, f2.x, a8[2*q]);
                a8[2*q+1] = fmaf(w, f2.y, a8[2*q+1]);
            }
        }
        float* dst = g_rep + ((size_t)blockIdx.x * 4 + bag) * D + cg * 8;
        *(float4*)(dst)     = make_float4(a8[0], a8[1], a8[2], a8[3]);
        *(float4*)(dst + 4) = make_float4(a8[4], a8[5], a8[6], a8[7]);
    }
}

// ---------------------------------------------------------------------------
// classifier kernel: out[b, c] = g_rep[b] . g_WcT[c] + bc[c]
// ---------------------------------------------------------------------------
#define CLS_BAGS 16
__global__ __launch_bounds__(256) void cls_kernel(
    const float* __restrict__ bc,
    float* __restrict__ out)
{
    __shared__ float rep_s[CLS_BAGS * D];   // 32 KB
    const int tid = threadIdx.x;
    const size_t bagBase = (size_t)blockIdx.x * CLS_BAGS;

    const float4* gr = (const float4*)(g_rep + bagBase * D);
    float4* rs = (float4*)rep_s;
#pragma unroll
    for (int i = 0; i < 8; i++) rs[tid + i * 256] = gr[tid + i * 256];
    __syncthreads();

    const int warp = tid >> 5, lane = tid & 31;
    for (int c = warp; c < NC; c += 8) {
        const float4* wc = (const float4*)&g_WcT[c * D];
        float4 w0 = wc[lane], w1 = wc[lane + 32], w2 = wc[lane + 64], w3 = wc[lane + 96];
        float bcv = bc[c];
#pragma unroll 4
        for (int b = 0; b < CLS_BAGS; b++) {
            const float4* rp = (const float4*)&rep_s[b * D];
            float4 r0 = rp[lane], r1 = rp[lane + 32], r2 = rp[lane + 64], r3 = rp[lane + 96];
            float s = 0.f;
            s = fmaf(r0.x, w0.x, s); s = fmaf(r0.y, w0.y, s);
            s = fmaf(r0.z, w0.z, s); s = fmaf(r0.w, w0.w, s);
            s = fmaf(r1.x, w1.x, s); s = fmaf(r1.y, w1.y, s);
            s = fmaf(r1.z, w1.z, s); s = fmaf(r1.w, w1.w, s);
            s = fmaf(r2.x, w2.x, s); s = fmaf(r2.y, w2.y, s);
            s = fmaf(r2.z, w2.z, s); s = fmaf(r2.w, w2.w, s);
            s = fmaf(r3.x, w3.x, s); s = fmaf(r3.y, w3.y, s);
            s = fmaf(r3.z, w3.z, s); s = fmaf(r3.w, w3.w, s);
            s += __shfl_xor_sync(0xffffffffu, s, 16);
            s += __shfl_xor_sync(0xffffffffu, s, 8);
            s += __shfl_xor_sync(0xffffffffu, s, 4);
            s += __shfl_xor_sync(0xffffffffu, s, 2);
            s += __shfl_xor_sync(0xffffffffu, s, 1);
            if (lane == 0) out[(bagBase + b) * NC + c] = s + bcv;
        }
    }
}

// ---------------------------------------------------------------------------
extern "C" void kernel_launch(void* const* d_in, const int* in_sizes, int n_in,
                              void* d_out, int out_size)
{
    const float* x  = (const float*)d_in[0];
    const float* W1 = (const float*)d_in[1];
    const float* W2 = (const float*)d_in[2];
    const float* Wc = (const float*)d_in[3];
    const float* bc = (const float*)d_in[4];
    float* out = (float*)d_out;

    cudaFuncSetAttribute(fused_kernel,
                         cudaFuncAttributeMaxDynamicSharedMemorySize, SMEM_SZ);

    prep_kernel<<<512 + (D * NC + 255) / 256, 256>>>(W1, Wc);
    fused_kernel<<<N_TOT / MT, 256, SMEM_SZ>>>(x, W2);
    cls_kernel<<<NBAGS / CLS_BAGS, 256>>>(bc, out);
}

// round 15
// speedup vs baseline: 1.4508x; 1.0864x over previous
#include <cuda_runtime.h>
#include <cuda_fp16.h>
#include <cstdint>
#include <math.h>

#define N_TOT   131072
#define D       512
#define DA      256
#define NH      4
#define NC      53
#define BAG     16
#define NBAGS   8192

#define MT      64          // CTA rows (4 bags)
#define KCH     32          // K chunk (64 bytes fp16) -- triple buffered
#define NCHUNK  (D / KCH)   // 16

// ---------------------------------------------------------------------------
// device scratch (allocation is forbidden)
// ---------------------------------------------------------------------------
__device__ float g_WcT[NC * D];
__device__ float g_rep[NBAGS * D];                 // bag representations
__device__ __align__(256) __half g_W1hH[DA * D];   // W1^T fp16, (n, k) k-contig

// ---------------------------------------------------------------------------
// helpers
// ---------------------------------------------------------------------------
__device__ __forceinline__ uint32_t smem_u32(const void* p) {
    uint32_t a;
    asm("{ .reg .u64 t; cvta.to.shared.u64 t, %1; cvt.u32.u64 %0, t; }" : "=r"(a) : "l"(p));
    return a;
}
__device__ __forceinline__ uint32_t sw128(uint32_t o) { return o ^ ((o >> 3) & 0x70); }
__device__ __forceinline__ uint32_t sw64 (uint32_t o) { return o ^ ((o >> 3) & 0x30); }

#define CP_ASYNC16(dst, src) \
    asm volatile("cp.async.cg.shared.global [%0], [%1], 16;" :: "r"(dst), "l"(src) : "memory")
#define CP_COMMIT() asm volatile("cp.async.commit_group;" ::: "memory")
#define CP_WAIT1()  asm volatile("cp.async.wait_group 1;" ::: "memory")
#define CP_WAIT0()  asm volatile("cp.async.wait_group 0;" ::: "memory")

__device__ __forceinline__ void ldsm_x4(uint32_t& r0, uint32_t& r1, uint32_t& r2,
                                        uint32_t& r3, uint32_t addr) {
    asm volatile("ldmatrix.sync.aligned.m8n8.x4.shared.b16 {%0,%1,%2,%3}, [%4];"
                 : "=r"(r0), "=r"(r1), "=r"(r2), "=r"(r3) : "r"(addr));
}
__device__ __forceinline__ void mma_f16(float* d, const uint32_t* a, const uint32_t* b) {
    asm volatile("mma.sync.aligned.m16n8k16.row.col.f32.f16.f16.f32 "
                 "{%0,%1,%2,%3}, {%4,%5,%6,%7}, {%8,%9}, {%0,%1,%2,%3};"
                 : "+f"(d[0]), "+f"(d[1]), "+f"(d[2]), "+f"(d[3])
                 : "r"(a[0]), "r"(a[1]), "r"(a[2]), "r"(a[3]), "r"(b[0]), "r"(b[1]));
}
__device__ __forceinline__ float ftanh(float v) {
    float t;
    asm("tanh.approx.f32 %0, %1;" : "=f"(t) : "f"(v));
    return t;
}
__device__ __forceinline__ uint32_t pack_h2(float a, float b) {
    __half2 h = __floats2half2_rn(a, b);
    return *reinterpret_cast<uint32_t*>(&h);
}

// ---------------------------------------------------------------------------
// prep kernel (merged): W1 -> fp16 transpose; Wc -> transpose
// ---------------------------------------------------------------------------
__global__ void prep_kernel(const float* __restrict__ W1,
                            const float* __restrict__ Wc) {
    int b = blockIdx.x;
    if (b < 512) {
        int i = b * 256 + threadIdx.x;
        int k = i >> 8, n = i & 255;
        g_W1hH[n * D + k] = __float2half_rn(W1[i]);
    } else {
        int i = (b - 512) * 256 + threadIdx.x;
        if (i < D * NC) {
            int d = i / NC, c = i - d * NC;
            g_WcT[c * D + d] = Wc[i];
        }
    }
}

// ---------------------------------------------------------------------------
// fused kernel: fp16 GEMM (64x256x512) + tanh/W2 + bag softmax
//               + bag weighted-sum (resident fp16 A) -> g_rep
// smem: A 64K @0 | B 3x16K @65536.  Epilogue-only data ALIASES the B region
// (W2s @65536, sRed4 @69632, sw @73728) — B stages are dead by then.
// ---------------------------------------------------------------------------
#define SOF_A    0
#define SOF_B    65536
#define BSTG     16384
#define SO_W2    65536
#define SO_RED   (65536 + 4096)
#define SO_SW    (65536 + 8192)
#define SMEM_SZ  (SOF_B + 3 * BSTG)   // 114688

__global__ void __launch_bounds__(256, 2) fused_kernel(
    const float* __restrict__ x,
    const float* __restrict__ W2)
{
    extern __shared__ char smem[];
    const uint32_t sb = smem_u32(smem);
    const int tid  = threadIdx.x;
    const int warp = tid >> 5;
    const int lane = tid & 31;
    const int wm = warp & 1;        // 0..1 : 32-row group
    const int wn = warp >> 1;       // 0..3 : 64-col group
    const size_t rowBase = (size_t)blockIdx.x * MT;
    const float* xrow = x + rowBase * D;

    // ---- prologue: B chunks 0 and 1 via cp.async (two commit groups) ----
#pragma unroll
    for (int i = 0; i < 4; i++) {
        int f = tid + i * 256;
        int n = f >> 2, k8 = f & 3;
        CP_ASYNC16(sb + SOF_B + sw64((uint32_t)(n * 64 + k8 * 16)),
                   g_W1hH + n * D + k8 * 8);
    }
    CP_COMMIT();
#pragma unroll
    for (int i = 0; i < 4; i++) {
        int f = tid + i * 256;
        int n = f >> 2, k8 = f & 3;
        CP_ASYNC16(sb + SOF_B + BSTG + sw64((uint32_t)(n * 64 + k8 * 16)),
                   g_W1hH + n * D + KCH + k8 * 8);
    }
    CP_COMMIT();

    // ---- full A tile: ldg fp32 -> fp16 -> STS (8 sub-tiles, sw128) ----
#pragma unroll
    for (int i = 0; i < 32; i++) {
        int f  = tid + i * 256;
        int r  = f >> 7;
        int k4 = (f & 127) << 2;
        float4 v = *(const float4*)&xrow[(size_t)r * D + k4];
        int chunk = k4 >> 6;
        int inner = (k4 & 63) << 1;
        *(uint2*)(smem + SOF_A + chunk * 8192 + sw128((uint32_t)(r * 128 + inner))) =
            make_uint2(pack_h2(v.x, v.y), pack_h2(v.z, v.w));
    }

    float acc[2][8][4];
#pragma unroll
    for (int mt = 0; mt < 2; mt++)
#pragma unroll
        for (int nt = 0; nt < 8; nt++)
#pragma unroll
            for (int q = 0; q < 4; q++) acc[mt][nt][q] = 0.0f;

    // ---- precomputed swizzled LDSM base offsets ----
    uint32_t preA[2];
#pragma unroll
    for (int mt = 0; mt < 2; mt++) {
        int row = wm * 32 + mt * 16 + ((lane >> 3) & 1) * 8 + (lane & 7);
        int kh  = (lane >> 4) * 8;
        preA[mt] = sw128((uint32_t)(row * 128 + kh * 2));
    }
    uint32_t preB[4];
#pragma unroll
    for (int np = 0; np < 4; np++) {
        int nrow = wn * 64 + np * 16 + (lane >> 4) * 8 + (lane & 7);
        int kh   = ((lane >> 3) & 1) * 8;
        preB[np] = sw64((uint32_t)(nrow * 64 + kh * 2));
    }

    // ---- main loop: 16 chunks, 3-stage B ring, prefetch distance 2 ----
#pragma unroll
    for (int c = 0; c < NCHUNK; c++) {
        if (c == NCHUNK - 1) CP_WAIT0(); else CP_WAIT1();
        __syncthreads();
        // issue B(c+2) into stage (c+2)%3 == (c-1)%3, last read in chunk c-1:
        // every warp passed the barrier above, so nobody still reads it.
        if (c + 2 < NCHUNK) {
#pragma unroll
            for (int i = 0; i < 4; i++) {
                int f = tid + i * 256;
                int n = f >> 2, k8 = f & 3;
                CP_ASYNC16(sb + SOF_B + ((c + 2) % 3) * BSTG +
                               sw64((uint32_t)(n * 64 + k8 * 16)),
                           g_W1hH + n * D + (c + 2) * KCH + k8 * 8);
            }
            CP_COMMIT();
        }

        const uint32_t stgA = sb + SOF_A + (c >> 1) * 8192;
        const uint32_t abyte = (uint32_t)((c & 1) * 64);
        const uint32_t stgB = sb + SOF_B + (c % 3) * BSTG;

        // batch all A fragments for this chunk (overlap LDSM latency)
        uint32_t ah[2][2][4];
#pragma unroll
        for (int ks = 0; ks < 2; ks++)
#pragma unroll
            for (int mt = 0; mt < 2; mt++)
                ldsm_x4(ah[ks][mt][0], ah[ks][mt][1], ah[ks][mt][2], ah[ks][mt][3],
                        stgA + (preA[mt] ^ (abyte + (uint32_t)(ks * 32))));

#pragma unroll
        for (int ks = 0; ks < 2; ks++) {
            const uint32_t kbB = (uint32_t)(ks * 32);
            uint32_t bh[8][2];
#pragma unroll
            for (int np = 0; np < 4; np++)
                ldsm_x4(bh[2*np][0], bh[2*np][1], bh[2*np+1][0], bh[2*np+1][1],
                        stgB + (preB[np] ^ kbB));
#pragma unroll
            for (int mt = 0; mt < 2; mt++)
#pragma unroll
                for (int nt = 0; nt < 8; nt++)
                    mma_f16(acc[mt][nt], ah[ks][mt], bh[nt]);
        }
    }

    // ---- B stages dead: load W2 into aliased region ----
    __syncthreads();
    float4* W2s = (float4*)(smem + SO_W2);
    if (tid < DA) W2s[tid] = ((const float4*)W2)[tid];
    __syncthreads();

    // ---- epilogue 1: tanh -> x W2 partials -> cross-warp reduce ----
    const int gid = lane >> 2, tig = lane & 3;
    float* sRed4 = (float*)(smem + SO_RED);   // [wn][64][4]

#pragma unroll
    for (int mt = 0; mt < 2; mt++) {
        float p0[4] = {0, 0, 0, 0}, p1[4] = {0, 0, 0, 0};
#pragma unroll
        for (int nt = 0; nt < 8; nt++) {
            int col = wn * 64 + nt * 8 + tig * 2;
            float4 wa = W2s[col], wb = W2s[col + 1];
            float t0 = ftanh(acc[mt][nt][0]);
            float t1 = ftanh(acc[mt][nt][1]);
            float t2 = ftanh(acc[mt][nt][2]);
            float t3 = ftanh(acc[mt][nt][3]);
            p0[0] = fmaf(t0, wa.x, fmaf(t1, wb.x, p0[0]));
            p0[1] = fmaf(t0, wa.y, fmaf(t1, wb.y, p0[1]));
            p0[2] = fmaf(t0, wa.z, fmaf(t1, wb.z, p0[2]));
            p0[3] = fmaf(t0, wa.w, fmaf(t1, wb.w, p0[3]));
            p1[0] = fmaf(t2, wa.x, fmaf(t3, wb.x, p1[0]));
            p1[1] = fmaf(t2, wa.y, fmaf(t3, wb.y, p1[1]));
            p1[2] = fmaf(t2, wa.z, fmaf(t3, wb.z, p1[2]));
            p1[3] = fmaf(t2, wa.w, fmaf(t3, wb.w, p1[3]));
        }
#pragma unroll
        for (int h = 0; h < 4; h++) {
            p0[h] += __shfl_xor_sync(0xffffffffu, p0[h], 1);
            p0[h] += __shfl_xor_sync(0xffffffffu, p0[h], 2);
            p1[h] += __shfl_xor_sync(0xffffffffu, p1[h], 1);
            p1[h] += __shfl_xor_sync(0xffffffffu, p1[h], 2);
        }
        if (tig == 0) {
            int r0 = wm * 32 + mt * 16 + gid;
            int r1 = r0 + 8;
#pragma unroll
            for (int h = 0; h < 4; h++) {
                sRed4[(wn * 64 + r0) * 4 + h] = p0[h];
                sRed4[(wn * 64 + r1) * 4 + h] = p1[h];
            }
        }
    }
    __syncthreads();

    // ---- epilogue 2: per-bag softmax (16-lane groups), head-mean weight ----
    float* sw = (float*)(smem + SO_SW);
    if (tid < MT) {
        float sc[4];
#pragma unroll
        for (int h = 0; h < 4; h++)
            sc[h] = sRed4[(0 * 64 + tid) * 4 + h] + sRed4[(1 * 64 + tid) * 4 + h]
                  + sRed4[(2 * 64 + tid) * 4 + h] + sRed4[(3 * 64 + tid) * 4 + h];
        float wsum = 0.f;
#pragma unroll
        for (int h = 0; h < 4; h++) {
            float mx = sc[h];
#pragma unroll
            for (int o = 1; o < 16; o <<= 1)
                mx = fmaxf(mx, __shfl_xor_sync(0xffffffffu, mx, o));
            float e = __expf(sc[h] - mx);
            float den = e;
#pragma unroll
            for (int o = 1; o < 16; o <<= 1)
                den += __shfl_xor_sync(0xffffffffu, den, o);
            wsum += e / den;
        }
        sw[tid] = 0.25f * wsum;
    }
    __syncthreads();

    // ---- epilogue 3: bag weighted sums from resident fp16 A -> g_rep ----
    {
        const int bag = tid >> 6;
        const int cg  = tid & 63;
        const int chunk = cg >> 3;
        const int innerb = (cg & 7) * 16;
        const uint32_t abase = sb + SOF_A + chunk * 8192;

        float a8[8];
#pragma unroll
        for (int j = 0; j < 8; j++) a8[j] = 0.f;
#pragma unroll
        for (int r = 0; r < BAG; r++) {
            int row = bag * BAG + r;
            float w = sw[row];
            uint4 v;
            asm volatile("ld.shared.v4.u32 {%0,%1,%2,%3}, [%4];"
                         : "=r"(v.x), "=r"(v.y), "=r"(v.z), "=r"(v.w)
                         : "r"(abase + sw128((uint32_t)(row * 128 + innerb))));
            const __half2* h2 = (const __half2*)&v;
#pragma unroll
            for (int q = 0; q < 4; q++) {
                float2 f2 = __half22float2(h2[q]);
                a8[2*q]   = fmaf(w, f2.x, a8[2*q]);
                a8[2*q+1] = fmaf(w, f2.y, a8[2*q+1]);
            }
        }
        float* dst = g_rep + ((size_t)blockIdx.x * 4 + bag) * D + cg * 8;
        *(float4*)(dst)     = make_float4(a8[0], a8[1], a8[2], a8[3]);
        *(float4*)(dst + 4) = make_float4(a8[4], a8[5], a8[6], a8[7]);
    }
}

// ---------------------------------------------------------------------------
// classifier kernel: out[b, c] = g_rep[b] . g_WcT[c] + bc[c]
// 8 bags / 256-thread block -> 1024 blocks (more parallelism, shorter tail)
// ---------------------------------------------------------------------------
#define CLS_BAGS 8
__global__ __launch_bounds__(256) void cls_kernel(
    const float* __restrict__ bc,
    float* __restrict__ out)
{
    __shared__ float rep_s[CLS_BAGS * D];   // 16 KB
    const int tid = threadIdx.x;
    const size_t bagBase = (size_t)blockIdx.x * CLS_BAGS;

    const float4* gr = (const float4*)(g_rep + bagBase * D);
    float4* rs = (float4*)rep_s;
#pragma unroll
    for (int i = 0; i < 4; i++) rs[tid + i * 256] = gr[tid + i * 256];
    __syncthreads();

    const int warp = tid >> 5, lane = tid & 31;
    for (int c = warp; c < NC; c += 8) {
        const float4* wc = (const float4*)&g_WcT[c * D];
        float4 w0 = wc[lane], w1 = wc[lane + 32], w2 = wc[lane + 64], w3 = wc[lane + 96];
        float bcv = bc[c];
#pragma unroll
        for (int b = 0; b < CLS_BAGS; b++) {
            const float4* rp = (const float4*)&rep_s[b * D];
            float4 r0 = rp[lane], r1 = rp[lane + 32], r2 = rp[lane + 64], r3 = rp[lane + 96];
            float s = 0.f;
            s = fmaf(r0.x, w0.x, s); s = fmaf(r0.y, w0.y, s);
            s = fmaf(r0.z, w0.z, s); s = fmaf(r0.w, w0.w, s);
            s = fmaf(r1.x, w1.x, s); s = fmaf(r1.y, w1.y, s);
            s = fmaf(r1.z, w1.z, s); s = fmaf(r1.w, w1.w, s);
            s = fmaf(r2.x, w2.x, s); s = fmaf(r2.y, w2.y, s);
            s = fmaf(r2.z, w2.z, s); s = fmaf(r2.w, w2.w, s);
            s = fmaf(r3.x, w3.x, s); s = fmaf(r3.y, w3.y, s);
            s = fmaf(r3.z, w3.z, s); s = fmaf(r3.w, w3.w, s);
            s += __shfl_xor_sync(0xffffffffu, s, 16);
            s += __shfl_xor_sync(0xffffffffu, s, 8);
            s += __shfl_xor_sync(0xffffffffu, s, 4);
            s += __shfl_xor_sync(0xffffffffu, s, 2);
            s += __shfl_xor_sync(0xffffffffu, s, 1);
            if (lane == 0) out[(bagBase + b) * NC + c] = s + bcv;
        }
    }
}

// ---------------------------------------------------------------------------
extern "C" void kernel_launch(void* const* d_in, const int* in_sizes, int n_in,
                              void* d_out, int out_size)
{
    const float* x  = (const float*)d_in[0];
    const float* W1 = (const float*)d_in[1];
    const float* W2 = (const float*)d_in[2];
    const float* Wc = (const float*)d_in[3];
    const float* bc = (const float*)d_in[4];
    float* out = (float*)d_out;

    cudaFuncSetAttribute(fused_kernel,
                         cudaFuncAttributeMaxDynamicSharedMemorySize, SMEM_SZ);

    prep_kernel<<<512 + (D * NC + 255) / 256, 256>>>(W1, Wc);
    fused_kernel<<<N_TOT / MT, 256, SMEM_SZ>>>(x, W2);
    cls_kernel<<<NBAGS / CLS_BAGS, 256>>>(bc, out);
}